// round 3
// baseline (speedup 1.0000x reference)
#include <cuda_runtime.h>
#include <cstdint>

#define NNODES 100000
#define F 16

__device__ __align__(16) float g_h1[NNODES * F];
__device__ __align__(16) float g_h2[NNODES * F];
__device__ int g_idx64;   // 1 if edge_index is int64, 0 if int32

__global__ void detect_kernel(const void* ei, int N) {
    const long long* p64 = (const long long*)ei;
    bool ok = true;
#pragma unroll
    for (int k = 0; k < 4; k++) {
        long long v = p64[k];
        if (v < 0 || v >= N) ok = false;
    }
    g_idx64 = ok ? 1 : 0;
}

__global__ void zero_kernel(int n4) {
    int i = blockIdx.x * blockDim.x + threadIdx.x;
    if (i < n4) {
        reinterpret_cast<float4*>(g_h1)[i] = make_float4(0.f, 0.f, 0.f, 0.f);
        reinterpret_cast<float4*>(g_h2)[i] = make_float4(0.f, 0.f, 0.f, 0.f);
    }
}

__device__ __forceinline__ void load_edge(const void* ei, int e, int E,
                                          long long& s, long long& d) {
    if (g_idx64) {
        const long long* p = (const long long*)ei;
        s = p[e];
        d = p[(size_t)E + e];
    } else {
        const int* p = (const int*)ei;
        s = p[e];
        d = p[(size_t)E + e];
    }
}

// Layer 1: in=4 per node, cat = 4+4+8 = 16
__global__ void __launch_bounds__(256) conv1_kernel(
    const float* __restrict__ x,
    const void* __restrict__ ei,
    const float* __restrict__ ea,
    const float* __restrict__ w1, const float* __restrict__ b1,
    const float* __restrict__ w2, const float* __restrict__ b2,
    int E)
{
    __shared__ float sw1[16 * F];
    __shared__ float sw2[F * F];
    __shared__ float sb1[F];
    __shared__ float sb2[F];
    int t = threadIdx.x;
    if (t < 256) { sw1[t] = w1[t]; sw2[t] = w2[t]; }
    if (t < F) { sb1[t] = b1[t]; sb2[t] = b2[t]; }
    __syncthreads();

    int e = blockIdx.x * blockDim.x + t;
    if (e >= E) return;

    long long s, d;
    load_edge(ei, e, E, s, d);

    float in[16];
    {
        float4 v;
        v = *reinterpret_cast<const float4*>(x + s * 4);
        in[0] = v.x; in[1] = v.y; in[2] = v.z; in[3] = v.w;
        v = *reinterpret_cast<const float4*>(x + d * 4);
        in[4] = v.x; in[5] = v.y; in[6] = v.z; in[7] = v.w;
        v = *reinterpret_cast<const float4*>(ea + (size_t)e * 8);
        in[8] = v.x; in[9] = v.y; in[10] = v.z; in[11] = v.w;
        v = *reinterpret_cast<const float4*>(ea + (size_t)e * 8 + 4);
        in[12] = v.x; in[13] = v.y; in[14] = v.z; in[15] = v.w;
    }

    float h[F];
#pragma unroll
    for (int j = 0; j < F; j++) h[j] = sb1[j];
#pragma unroll
    for (int i = 0; i < 16; i++) {
        float xi = in[i];
#pragma unroll
        for (int j = 0; j < F; j++) h[j] = fmaf(xi, sw1[i * F + j], h[j]);
    }
#pragma unroll
    for (int j = 0; j < F; j++) h[j] = fmaxf(h[j], 0.f);

    float o[F];
#pragma unroll
    for (int j = 0; j < F; j++) o[j] = sb2[j];
#pragma unroll
    for (int i = 0; i < F; i++) {
        float hi = h[i];
#pragma unroll
        for (int j = 0; j < F; j++) o[j] = fmaf(hi, sw2[i * F + j], o[j]);
    }

    int* op = reinterpret_cast<int*>(g_h1 + s * F);
#pragma unroll
    for (int j = 0; j < F; j++) {
        float v = fmaxf(o[j], 0.f);
        atomicMax(op + j, __float_as_int(v));   // unused return -> REDG.MAX
    }
}

// Layer 2: in=16 per node, cat = 16+16+8 = 40
__global__ void __launch_bounds__(256) conv2_kernel(
    const void* __restrict__ ei,
    const float* __restrict__ ea,
    const float* __restrict__ w1, const float* __restrict__ b1,
    const float* __restrict__ w2, const float* __restrict__ b2,
    int E)
{
    __shared__ float sw1[40 * F];   // 640
    __shared__ float sw2[F * F];    // 256
    __shared__ float sb1[F];
    __shared__ float sb2[F];
    int t = threadIdx.x;
    for (int k = t; k < 40 * F; k += 256) sw1[k] = w1[k];
    if (t < 256) sw2[t] = w2[t];
    if (t < F) { sb1[t] = b1[t]; sb2[t] = b2[t]; }
    __syncthreads();

    int e = blockIdx.x * blockDim.x + t;
    if (e >= E) return;

    long long s, d;
    load_edge(ei, e, E, s, d);

    float in[40];
    {
        const float4* ps = reinterpret_cast<const float4*>(g_h1 + s * F);
        const float4* pd = reinterpret_cast<const float4*>(g_h1 + d * F);
#pragma unroll
        for (int q = 0; q < 4; q++) {
            float4 v = ps[q];
            in[q * 4 + 0] = v.x; in[q * 4 + 1] = v.y; in[q * 4 + 2] = v.z; in[q * 4 + 3] = v.w;
        }
#pragma unroll
        for (int q = 0; q < 4; q++) {
            float4 v = pd[q];
            in[16 + q * 4 + 0] = v.x; in[16 + q * 4 + 1] = v.y; in[16 + q * 4 + 2] = v.z; in[16 + q * 4 + 3] = v.w;
        }
        float4 v;
        v = *reinterpret_cast<const float4*>(ea + (size_t)e * 8);
        in[32] = v.x; in[33] = v.y; in[34] = v.z; in[35] = v.w;
        v = *reinterpret_cast<const float4*>(ea + (size_t)e * 8 + 4);
        in[36] = v.x; in[37] = v.y; in[38] = v.z; in[39] = v.w;
    }

    float h[F];
#pragma unroll
    for (int j = 0; j < F; j++) h[j] = sb1[j];
#pragma unroll
    for (int i = 0; i < 40; i++) {
        float xi = in[i];
#pragma unroll
        for (int j = 0; j < F; j++) h[j] = fmaf(xi, sw1[i * F + j], h[j]);
    }
#pragma unroll
    for (int j = 0; j < F; j++) h[j] = fmaxf(h[j], 0.f);

    float o[F];
#pragma unroll
    for (int j = 0; j < F; j++) o[j] = sb2[j];
#pragma unroll
    for (int i = 0; i < F; i++) {
        float hi = h[i];
#pragma unroll
        for (int j = 0; j < F; j++) o[j] = fmaf(hi, sw2[i * F + j], o[j]);
    }

    int* op = reinterpret_cast<int*>(g_h2 + s * F);
#pragma unroll
    for (int j = 0; j < F; j++) {
        float v = fmaxf(o[j], 0.f);
        atomicMax(op + j, __float_as_int(v));
    }
}

// Final node MLP: out = relu(h @ l1_w + l1_b) @ l2_w + l2_b
__global__ void __launch_bounds__(256) node_mlp_kernel(
    const float* __restrict__ l1w, const float* __restrict__ l1b,
    const float* __restrict__ l2w, const float* __restrict__ l2b,
    float* __restrict__ out, int n)
{
    __shared__ float sw1[F * F];
    __shared__ float sb1[F];
    __shared__ float sw2[F];
    __shared__ float sb2;
    int t = threadIdx.x;
    if (t < 256) sw1[t] = l1w[t];
    if (t < F) { sb1[t] = l1b[t]; sw2[t] = l2w[t]; }
    if (t == 0) sb2 = l2b[0];
    __syncthreads();

    int i = blockIdx.x * blockDim.x + t;
    if (i >= n) return;

    float in[F];
    const float4* ph = reinterpret_cast<const float4*>(g_h2 + (size_t)i * F);
#pragma unroll
    for (int q = 0; q < 4; q++) {
        float4 v = ph[q];
        in[q * 4 + 0] = v.x; in[q * 4 + 1] = v.y; in[q * 4 + 2] = v.z; in[q * 4 + 3] = v.w;
    }

    float h[F];
#pragma unroll
    for (int j = 0; j < F; j++) h[j] = sb1[j];
#pragma unroll
    for (int k = 0; k < F; k++) {
        float xi = in[k];
#pragma unroll
        for (int j = 0; j < F; j++) h[j] = fmaf(xi, sw1[k * F + j], h[j]);
    }
    float acc = sb2;
#pragma unroll
    for (int j = 0; j < F; j++) acc += fmaxf(h[j], 0.f) * sw2[j];

    out[i] = acc;
}

extern "C" void kernel_launch(void* const* d_in, const int* in_sizes, int n_in,
                              void* d_out, int out_size)
{
    const float* x     = (const float*)d_in[0];
    const void*  ei    = d_in[1];
    const float* ea    = (const float*)d_in[2];
    const float* c1_w1 = (const float*)d_in[3];
    const float* c1_b1 = (const float*)d_in[4];
    const float* c1_w2 = (const float*)d_in[5];
    const float* c1_b2 = (const float*)d_in[6];
    const float* c2_w1 = (const float*)d_in[7];
    const float* c2_b1 = (const float*)d_in[8];
    const float* c2_w2 = (const float*)d_in[9];
    const float* c2_b2 = (const float*)d_in[10];
    const float* l1_w  = (const float*)d_in[11];
    const float* l1_b  = (const float*)d_in[12];
    const float* l2_w  = (const float*)d_in[13];
    const float* l2_b  = (const float*)d_in[14];

    int N = in_sizes[0] / 4;           // x is [N,4]
    int E = in_sizes[2] / 8;           // edge_attr is [E,8]
    float* out = (float*)d_out;

    detect_kernel<<<1, 1>>>(ei, N);

    // zero both scratch buffers (atomicMax baseline = 0 == PyG's empty-segment fill)
    {
        int n4 = N * F / 4;
        int blocks = (n4 + 255) / 256;
        zero_kernel<<<blocks, 256>>>(n4);
    }

    int eblocks = (E + 255) / 256;
    conv1_kernel<<<eblocks, 256>>>(x, ei, ea, c1_w1, c1_b1, c1_w2, c1_b2, E);
    conv2_kernel<<<eblocks, 256>>>(ei, ea, c2_w1, c2_b1, c2_w2, c2_b2, E);

    int nblocks = (N + 255) / 256;
    node_mlp_kernel<<<nblocks, 256>>>(l1_w, l1_b, l2_w, l2_b, out, N);
}